// round 16
// baseline (speedup 1.0000x reference)
#include <cuda_runtime.h>
#include <cuda_fp16.h>
#include <cstdint>
#include <math.h>

#define N_NODES 100000
#define N_EDGES 1600000
#define C_IN 500
#define HIDDEN 256
#define C_OUT 50
#define C_PAD 64
#define K_HALF 5
#define NB_SCAN 391

// ---------------- scratch (static device globals; no allocation) ----------------
__device__ __half g_w1h[256 * 512];        // W1^T fp16 padded: [n=256][k=512]
__device__ __half g_bufA[N_NODES * C_PAD];
__device__ __half g_bufB[N_NODES * C_PAD];
__device__ float  g_hidden[5000000];
__device__ float  g_dinv[N_NODES];
__device__ int    g_cnt_src[N_NODES];
__device__ int    g_cnt_dst[N_NODES];
__device__ int    g_cursor[N_NODES];
__device__ int    g_rowptr[N_NODES + 1];
__device__ int2   g_csr[N_EDGES];
__device__ int    g_partial[512];

// ---------------- graph preprocessing ----------------
__global__ void zero_kernel() {
    int i = blockIdx.x * blockDim.x + threadIdx.x;
    if (i < N_NODES) { g_cnt_src[i] = 0; g_cnt_dst[i] = 0; g_cursor[i] = 0; }
}

__global__ void count_kernel(const int* __restrict__ ei) {
    int i = blockIdx.x * blockDim.x + threadIdx.x;
    if (i < N_EDGES) {
        atomicAdd(&g_cnt_src[ei[i]], 1);
        atomicAdd(&g_cnt_dst[ei[N_EDGES + i]], 1);
    }
}

__global__ void scan_partial_kernel() {
    __shared__ int sh[256];
    int i = blockIdx.x * 256 + threadIdx.x;
    int v = (i < N_NODES) ? g_cnt_dst[i] : 0;
    if (i < N_NODES) {
        int d = g_cnt_src[i];
        g_dinv[i] = d > 0 ? rsqrtf((float)d) : 0.0f;
    }
    sh[threadIdx.x] = v;
    __syncthreads();
    for (int s = 128; s > 0; s >>= 1) {
        if (threadIdx.x < s) sh[threadIdx.x] += sh[threadIdx.x + s];
        __syncthreads();
    }
    if (threadIdx.x == 0) g_partial[blockIdx.x] = sh[0];
}

__global__ void scan_offsets_kernel() {
    int acc = 0;
    for (int b = 0; b < NB_SCAN; b++) { int v = g_partial[b]; g_partial[b] = acc; acc += v; }
    g_rowptr[N_NODES] = N_EDGES;
}

__global__ void scan_final_kernel() {
    __shared__ int sh[256];
    int i = blockIdx.x * 256 + threadIdx.x;
    int v = (i < N_NODES) ? g_cnt_dst[i] : 0;
    sh[threadIdx.x] = v;
    __syncthreads();
    for (int s = 1; s < 256; s <<= 1) {
        int t = (threadIdx.x >= s) ? sh[threadIdx.x - s] : 0;
        __syncthreads();
        sh[threadIdx.x] += t;
        __syncthreads();
    }
    if (i < N_NODES) g_rowptr[i] = g_partial[blockIdx.x] + sh[threadIdx.x] - v;
}

__global__ void fill_kernel(const int* __restrict__ ei) {
    int i = blockIdx.x * blockDim.x + threadIdx.x;
    if (i < N_EDGES) {
        int s = ei[i], d = ei[N_EDGES + i];
        int pos = g_rowptr[d] + atomicAdd(&g_cursor[d], 1);
        float w = g_dinv[s] * g_dinv[d];
        g_csr[pos] = make_int2(s, __float_as_int(w));
    }
}

// ---------------- W1 -> fp16 transposed scratch: g_w1h[n][k] ----------------
__global__ void w1cvt_kernel(const float* __restrict__ W1) {
    int idx = blockIdx.x * 256 + threadIdx.x;
    if (idx < 256 * 512) {
        int n = idx >> 9, k = idx & 511;
        float v = (k < C_IN) ? W1[(size_t)k * HIDDEN + n] : 0.f;
        g_w1h[idx] = __float2half_rn(v);
    }
}

// ---------------- ldmatrix helper ----------------
__device__ __forceinline__ void ldsm_x4(unsigned int& r0, unsigned int& r1,
                                        unsigned int& r2, unsigned int& r3,
                                        unsigned int addr) {
    asm volatile("ldmatrix.sync.aligned.m8n8.x4.shared.b16 {%0,%1,%2,%3}, [%4];"
                 : "=r"(r0), "=r"(r1), "=r"(r2), "=r"(r3) : "r"(addr));
}

// ---------------- FUSED GEMM1+GEMM2 (fp16 mma, BM=128, 512 threads, BK=64) ----------------
#define A16_ST 72
#define A16_BYTES (128 * A16_ST * 2)    /* 18432 */
#define B16_BYTES (256 * A16_ST * 2)    /* 36864 */
#define SH_ST 264
#define GEMM_SMEM (2 * (A16_BYTES + B16_BYTES))  /* 110592 */
#define G_THREADS 512

__global__ void __launch_bounds__(G_THREADS) gemm12_tc_kernel(
    const float* __restrict__ A, const float* __restrict__ bias,
    const float* __restrict__ W2, const float* __restrict__ b2, const float* __restrict__ temp) {
    extern __shared__ float smem[];
    __half* smh = (__half*)smem;
    __half* sAb[2] = { smh, smh + (A16_BYTES + B16_BYTES) / 2 };
    __half* sBb[2] = { smh + A16_BYTES / 2, smh + (2 * A16_BYTES + B16_BYTES) / 2 };

    const int tid = threadIdx.x;
    const int m0 = blockIdx.x * 128;
    const int wid = tid >> 5, lane = tid & 31;
    const int warp_m = wid >> 2, warp_n = wid & 3;
    const int r = lane >> 2, c = lane & 3;

    const int aRowIn = lane & 15;
    const int aKoff  = (lane >> 4) * 8;
    const int bQuad  = lane >> 3;
    const int bRowIn = lane & 7;
    const int bNloc  = ((bQuad >> 1) * 8) + bRowIn;
    const int bKoff  = (bQuad & 1) * 8;

    float acc[2][8][4];
#pragma unroll
    for (int mt = 0; mt < 2; mt++)
#pragma unroll
        for (int nt = 0; nt < 8; nt++)
#pragma unroll
            for (int i = 0; i < 4; i++) acc[mt][nt][i] = 0.0f;

    float4 astg[4];

    auto ldgA = [&](int t) {
        int k0 = t * 64;
#pragma unroll
        for (int j = 0; j < 4; j++) {
            int idx = tid + j * G_THREADS;
            int row = idx >> 4, kv = (idx & 15) * 4;
            int gm = m0 + row, gk = k0 + kv;
            if (gm < N_NODES && gk < C_IN) {
                astg[j] = *(const float4*)(A + (size_t)gm * C_IN + gk);
            } else {
                astg[j] = make_float4(0.f, 0.f, 0.f, 0.f);
            }
        }
    };
    auto stsA = [&](int t) {
        __half* dstb = sAb[t & 1];
#pragma unroll
        for (int j = 0; j < 4; j++) {
            int idx = tid + j * G_THREADS;
            int row = idx >> 4, kv = (idx & 15) * 4;
            half2 h0 = __floats2half2_rn(astg[j].x, astg[j].y);
            half2 h1 = __floats2half2_rn(astg[j].z, astg[j].w);
            uint2 p;
            p.x = *reinterpret_cast<unsigned int*>(&h0);
            p.y = *reinterpret_cast<unsigned int*>(&h1);
            *(uint2*)(dstb + row * A16_ST + kv) = p;
        }
    };
    auto cpB = [&](int t) {
        __half* dstb = sBb[t & 1];
        int k0 = t * 64;
#pragma unroll
        for (int j = 0; j < 4; j++) {
            int idx = tid + j * G_THREADS;
            int n = idx >> 3, part = idx & 7;
            const __half* src = g_w1h + (size_t)n * 512 + k0 + part * 8;
            unsigned int dst = (unsigned int)__cvta_generic_to_shared(dstb + n * A16_ST + part * 8);
            asm volatile("cp.async.cg.shared.global [%0], [%1], 16, 16;"
                         :: "r"(dst), "l"(src));
        }
        asm volatile("cp.async.commit_group;");
    };

    const int NT = 8;

    ldgA(0);
    stsA(0);
    cpB(0);
    ldgA(1);

    for (int t = 0; t < NT; t++) {
        if (t + 1 < NT) {
            stsA(t + 1);
            cpB(t + 1);
            if (t + 2 < NT) ldgA(t + 2);
            asm volatile("cp.async.wait_group 1;");
        } else {
            asm volatile("cp.async.wait_group 0;");
        }
        __syncthreads();

        const __half* sA = sAb[t & 1];
        const __half* sB = sBb[t & 1];

        unsigned int aB[2], bB[4];
#pragma unroll
        for (int mt = 0; mt < 2; mt++)
            aB[mt] = (unsigned int)__cvta_generic_to_shared(
                sA + (warp_m * 32 + mt * 16 + aRowIn) * A16_ST + aKoff);
#pragma unroll
        for (int p = 0; p < 4; p++)
            bB[p] = (unsigned int)__cvta_generic_to_shared(
                sB + (warp_n * 64 + p * 16 + bNloc) * A16_ST + bKoff);

#pragma unroll
        for (int ks = 0; ks < 4; ks++) {
            const int off = ks * 32;
            unsigned int af[2][4], bf[8][2];
#pragma unroll
            for (int mt = 0; mt < 2; mt++)
                ldsm_x4(af[mt][0], af[mt][1], af[mt][2], af[mt][3], aB[mt] + off);
#pragma unroll
            for (int p = 0; p < 4; p++)
                ldsm_x4(bf[2 * p][0], bf[2 * p][1], bf[2 * p + 1][0], bf[2 * p + 1][1],
                        bB[p] + off);
#pragma unroll
            for (int mt = 0; mt < 2; mt++)
#pragma unroll
                for (int nt = 0; nt < 8; nt++) {
                    asm volatile(
                        "mma.sync.aligned.m16n8k16.row.col.f32.f16.f16.f32 "
                        "{%0,%1,%2,%3}, {%4,%5,%6,%7}, {%8,%9}, {%0,%1,%2,%3};\n"
                        : "+f"(acc[mt][nt][0]), "+f"(acc[mt][nt][1]),
                          "+f"(acc[mt][nt][2]), "+f"(acc[mt][nt][3])
                        : "r"(af[mt][0]), "r"(af[mt][1]), "r"(af[mt][2]), "r"(af[mt][3]),
                          "r"(bf[nt][0]), "r"(bf[nt][1]));
                }
        }
        __syncthreads();
    }

    // ---- stage h tile + W2^T ----
    __half* sH   = smh;
    __half* sW2t = smh + 128 * SH_ST;

#pragma unroll
    for (int mt = 0; mt < 2; mt++) {
#pragma unroll
        for (int nt = 0; nt < 8; nt++) {
            int col = warp_n * 64 + nt * 8 + c * 2;
            float2 bv = *(const float2*)(bias + col);
            int row0 = warp_m * 32 + mt * 16 + r;
            float v0 = fmaxf(acc[mt][nt][0] + bv.x, 0.f);
            float v1 = fmaxf(acc[mt][nt][1] + bv.y, 0.f);
            *(half2*)(sH + row0 * SH_ST + col) = __floats2half2_rn(v0, v1);
            float v2 = fmaxf(acc[mt][nt][2] + bv.x, 0.f);
            float v3 = fmaxf(acc[mt][nt][3] + bv.y, 0.f);
            *(half2*)(sH + (row0 + 8) * SH_ST + col) = __floats2half2_rn(v2, v3);
        }
    }
    for (int idx = tid; idx < 64 * 256; idx += G_THREADS) {
        int n = idx >> 8, k = idx & 255;
        float v = (n < C_OUT) ? __ldg(W2 + (size_t)k * C_OUT + n) : 0.f;
        sW2t[n * SH_ST + k] = __float2half_rn(v);
    }
    __syncthreads();

    // ---- second GEMM ----
    float acc2[2][2][4];
#pragma unroll
    for (int mt = 0; mt < 2; mt++)
#pragma unroll
        for (int nt = 0; nt < 2; nt++)
#pragma unroll
            for (int i = 0; i < 4; i++) acc2[mt][nt][i] = 0.0f;

    unsigned int aB2[2], bB2;
#pragma unroll
    for (int mt = 0; mt < 2; mt++)
        aB2[mt] = (unsigned int)__cvta_generic_to_shared(
            sH + (warp_m * 32 + mt * 16 + aRowIn) * SH_ST + aKoff);
    bB2 = (unsigned int)__cvta_generic_to_shared(
        sW2t + (warp_n * 16 + bNloc) * SH_ST + bKoff);

#pragma unroll
    for (int ks = 0; ks < 16; ks++) {
        const int off = ks * 32;
        unsigned int a[2][4], b[2][2];
#pragma unroll
        for (int mt = 0; mt < 2; mt++)
            ldsm_x4(a[mt][0], a[mt][1], a[mt][2], a[mt][3], aB2[mt] + off);
        ldsm_x4(b[0][0], b[0][1], b[1][0], b[1][1], bB2 + off);
#pragma unroll
        for (int mt = 0; mt < 2; mt++)
#pragma unroll
            for (int nt = 0; nt < 2; nt++) {
                asm volatile(
                    "mma.sync.aligned.m16n8k16.row.col.f32.f16.f16.f32 "
                    "{%0,%1,%2,%3}, {%4,%5,%6,%7}, {%8,%9}, {%0,%1,%2,%3};\n"
                    : "+f"(acc2[mt][nt][0]), "+f"(acc2[mt][nt][1]),
                      "+f"(acc2[mt][nt][2]), "+f"(acc2[mt][nt][3])
                    : "r"(a[mt][0]), "r"(a[mt][1]), "r"(a[mt][2]), "r"(a[mt][3]),
                      "r"(b[nt][0]), "r"(b[nt][1]));
            }
    }

    // ---- epilogue2 ----
    float t0 = __ldg(temp);
#pragma unroll
    for (int mt = 0; mt < 2; mt++) {
#pragma unroll
        for (int nt = 0; nt < 2; nt++) {
            int col = warp_n * 16 + nt * 8 + c * 2;
#pragma unroll
            for (int hh = 0; hh < 2; hh++) {
                int gm = m0 + warp_m * 32 + mt * 16 + hh * 8 + r;
                if (gm >= N_NODES) continue;
                __half* arow = g_bufA + (size_t)gm * C_PAD;
                if (col < C_OUT) {
                    float v0 = acc2[mt][nt][hh * 2 + 0] + __ldg(b2 + col);
                    float v1 = acc2[mt][nt][hh * 2 + 1] + __ldg(b2 + col + 1);
                    *(half2*)(arow + col) = __floats2half2_rn(v0, v1);
                    float* hrow = g_hidden + (size_t)gm * C_OUT + col;
                    hrow[0] = t0 * v0;
                    hrow[1] = t0 * v1;
                } else {
                    *(half2*)(arow + col) = __floats2half2_rn(0.f, 0.f);
                }
            }
        }
    }
}

// ---------------- pulls: 4 edges per warp-instruction (4 groups x 8 lanes) ----------------
// MODE 0: xin->xout. MODE 1: + hidden += t*v. MODE 2: final, fused log_softmax -> out.
template <int MODE>
__device__ __forceinline__ void pull_body8(
    const __half* __restrict__ xin, __half* __restrict__ xout,
    const float* __restrict__ temp, int kidx, float* __restrict__ out) {
    int node = (blockIdx.x * blockDim.x + threadIdx.x) >> 5;
    if (node >= N_NODES) return;
    int lane = threadIdx.x & 31;
    int lg = lane & 7, grp = lane >> 3;
    int beg = g_rowptr[node], end = g_rowptr[node + 1];

    float acc0 = 0.f, acc1 = 0.f, acc2 = 0.f, acc3 = 0.f;
    float acc4 = 0.f, acc5 = 0.f, acc6 = 0.f, acc7 = 0.f;

    for (int e = beg; e < end; e += 4) {
        int ee = e + grp;
        int src = 0;
        float w = 0.f;
        if (ee < end) {
            int2 ed = __ldg(&g_csr[ee]);
            src = ed.x;
            w = __int_as_float(ed.y);
        }
        uint4 rv = *((const uint4*)(xin + (size_t)src * C_PAD) + lg);
        half2 h0 = *reinterpret_cast<half2*>(&rv.x);
        half2 h1 = *reinterpret_cast<half2*>(&rv.y);
        half2 h2 = *reinterpret_cast<half2*>(&rv.z);
        half2 h3 = *reinterpret_cast<half2*>(&rv.w);
        float2 f0 = __half22float2(h0), f1 = __half22float2(h1);
        float2 f2 = __half22float2(h2), f3 = __half22float2(h3);
        acc0 += w * f0.x; acc1 += w * f0.y;
        acc2 += w * f1.x; acc3 += w * f1.y;
        acc4 += w * f2.x; acc5 += w * f2.y;
        acc6 += w * f3.x; acc7 += w * f3.y;
    }

    // reduce the 4 groups (lanes lg, lg+8, lg+16, lg+24)
#pragma unroll
    for (int o = 8; o <= 16; o <<= 1) {
        acc0 += __shfl_xor_sync(0xffffffffu, acc0, o);
        acc1 += __shfl_xor_sync(0xffffffffu, acc1, o);
        acc2 += __shfl_xor_sync(0xffffffffu, acc2, o);
        acc3 += __shfl_xor_sync(0xffffffffu, acc3, o);
        acc4 += __shfl_xor_sync(0xffffffffu, acc4, o);
        acc5 += __shfl_xor_sync(0xffffffffu, acc5, o);
        acc6 += __shfl_xor_sync(0xffffffffu, acc6, o);
        acc7 += __shfl_xor_sync(0xffffffffu, acc7, o);
    }

    if (MODE < 2) {
        if (grp == 0) {
            half2 o0 = __floats2half2_rn(acc0, acc1);
            half2 o1 = __floats2half2_rn(acc2, acc3);
            half2 o2 = __floats2half2_rn(acc4, acc5);
            half2 o3 = __floats2half2_rn(acc6, acc7);
            uint4 ov;
            ov.x = *reinterpret_cast<unsigned int*>(&o0);
            ov.y = *reinterpret_cast<unsigned int*>(&o1);
            ov.z = *reinterpret_cast<unsigned int*>(&o2);
            ov.w = *reinterpret_cast<unsigned int*>(&o3);
            *((uint4*)(xout + (size_t)node * C_PAD) + lg) = ov;
            if (MODE == 1) {
                float t = __ldg(temp + kidx);
                int col = lg * 8;
                float* hrow = g_hidden + (size_t)node * C_OUT + col;
                if (col + 1 < C_OUT) { hrow[0] += t * acc0; hrow[1] += t * acc1; }
                if (col + 3 < C_OUT) { hrow[2] += t * acc2; hrow[3] += t * acc3; }
                if (col + 5 < C_OUT) { hrow[4] += t * acc4; hrow[5] += t * acc5; }
                if (col + 7 < C_OUT) { hrow[6] += t * acc6; hrow[7] += t * acc7; }
            }
        }
    } else {
        // final: v = hidden + t*acc on group 0, then warp log_softmax
        float t = __ldg(temp + K_HALF);
        float v[8];
        int col = lg * 8;
        float m = -INFINITY;
        if (grp == 0) {
            float a[8] = {acc0, acc1, acc2, acc3, acc4, acc5, acc6, acc7};
            const float* hrow = g_hidden + (size_t)node * C_OUT + col;
#pragma unroll
            for (int j = 0; j < 8; j++) {
                if (col + j < C_OUT) {
                    v[j] = hrow[j] + t * a[j];
                    m = fmaxf(m, v[j]);
                } else {
                    v[j] = -INFINITY;
                }
            }
        }
#pragma unroll
        for (int o = 16; o > 0; o >>= 1) m = fmaxf(m, __shfl_xor_sync(0xffffffffu, m, o));
        float s = 0.f;
        if (grp == 0) {
#pragma unroll
            for (int j = 0; j < 8; j++)
                if (col + j < C_OUT) s += expf(v[j] - m);
        }
#pragma unroll
        for (int o = 16; o > 0; o >>= 1) s += __shfl_xor_sync(0xffffffffu, s, o);
        float l = m + logf(s);
        if (grp == 0) {
            float* orow = out + (size_t)node * C_OUT + col;
#pragma unroll
            for (int j = 0; j < 8; j += 2) {
                if (col + j + 1 < C_OUT) {
                    float2 o2;
                    o2.x = v[j] - l;
                    o2.y = v[j + 1] - l;
                    *(float2*)(orow + j) = o2;
                }
            }
        }
    }
}

__global__ void __launch_bounds__(256) pull1_kernel() {
    pull_body8<0>(g_bufA, g_bufB, nullptr, 0, nullptr);
}
__global__ void __launch_bounds__(256) pull2_kernel(const float* __restrict__ temp, int kidx) {
    pull_body8<1>(g_bufB, g_bufA, temp, kidx, nullptr);
}
__global__ void __launch_bounds__(256) pull2_final_kernel(
    const float* __restrict__ temp, float* __restrict__ out) {
    pull_body8<2>(g_bufB, nullptr, temp, 0, out);
}

// ---------------- launch ----------------
extern "C" void kernel_launch(void* const* d_in, const int* in_sizes, int n_in,
                              void* d_out, int out_size) {
    const float* x    = (const float*)d_in[0];
    const int*   ei   = (const int*)d_in[1];
    const float* W1   = (const float*)d_in[2];
    const float* b1   = (const float*)d_in[3];
    const float* W2   = (const float*)d_in[4];
    const float* b2   = (const float*)d_in[5];
    const float* temp = (const float*)d_in[6];
    float* out = (float*)d_out;

    int nb_nodes = (N_NODES + 255) / 256;
    int nb_edges = (N_EDGES + 255) / 256;

    static int attr_set = 0;
    if (!attr_set) {
        cudaFuncSetAttribute(gemm12_tc_kernel, cudaFuncAttributeMaxDynamicSharedMemorySize, GEMM_SMEM);
        attr_set = 1;
    }

    w1cvt_kernel<<<512, 256>>>(W1);                                           // 0
    zero_kernel<<<nb_nodes, 256>>>();                                         // 1
    count_kernel<<<nb_edges, 256>>>(ei);                                      // 2
    gemm12_tc_kernel<<<(N_NODES + 127) / 128, G_THREADS, GEMM_SMEM>>>(x, b1, W2, b2, temp);  // 3 <- profiled
    scan_partial_kernel<<<NB_SCAN, 256>>>();                                  // 4
    scan_offsets_kernel<<<1, 1>>>();                                          // 5
    scan_final_kernel<<<NB_SCAN, 256>>>();                                    // 6
    fill_kernel<<<nb_edges, 256>>>(ei);                                       // 7

    int pull_grid = (N_NODES * 32 + 255) / 256;
    for (int k = 0; k < K_HALF - 1; k++) {
        pull1_kernel<<<pull_grid, 256>>>();
        pull2_kernel<<<pull_grid, 256>>>(temp, k + 1);
    }
    pull1_kernel<<<pull_grid, 256>>>();
    pull2_final_kernel<<<pull_grid, 256>>>(temp, out);
}

// round 17
// speedup vs baseline: 1.1079x; 1.1079x over previous
#include <cuda_runtime.h>
#include <cuda_fp16.h>
#include <cstdint>
#include <math.h>

#define N_NODES 100000
#define N_EDGES 1600000
#define C_IN 500
#define HIDDEN 256
#define C_OUT 50
#define C_PAD 64
#define K_HALF 5
#define NB_SCAN 391

// ---------------- scratch (static device globals; zero-initialized at load) ----------------
__device__ __half g_w1h[256 * 512];
__device__ __half g_bufA[N_NODES * C_PAD];
__device__ __half g_bufB[N_NODES * C_PAD];
__device__ float  g_hidden[5000000];
__device__ float  g_dinv[N_NODES];
__device__ int    g_cnt_src[N_NODES];
__device__ int    g_cnt_dst[N_NODES];
__device__ int    g_cursor[N_NODES];
__device__ int    g_rowptr[N_NODES + 1];
__device__ int2   g_csr[N_EDGES];
__device__ int    g_partial[512];

// ---------------- graph preprocessing ----------------
// counters are zeroed by the END of the previous replay (pull2_final); first call
// relies on static zero-initialization of __device__ globals.
__global__ void count_kernel(const int* __restrict__ ei) {
    int i = blockIdx.x * blockDim.x + threadIdx.x;
    if (i < N_EDGES) {
        atomicAdd(&g_cnt_src[ei[i]], 1);
        atomicAdd(&g_cnt_dst[ei[N_EDGES + i]], 1);
    }
}

__global__ void scan_partial_kernel() {
    __shared__ int sh[256];
    int i = blockIdx.x * 256 + threadIdx.x;
    int v = (i < N_NODES) ? g_cnt_dst[i] : 0;
    if (i < N_NODES) {
        int d = g_cnt_src[i];
        g_dinv[i] = d > 0 ? rsqrtf((float)d) : 0.0f;
    }
    sh[threadIdx.x] = v;
    __syncthreads();
    for (int s = 128; s > 0; s >>= 1) {
        if (threadIdx.x < s) sh[threadIdx.x] += sh[threadIdx.x + s];
        __syncthreads();
    }
    if (threadIdx.x == 0) g_partial[blockIdx.x] = sh[0];
}

__global__ void scan_offsets_kernel() {
    int acc = 0;
    for (int b = 0; b < NB_SCAN; b++) { int v = g_partial[b]; g_partial[b] = acc; acc += v; }
    g_rowptr[N_NODES] = N_EDGES;
}

__global__ void scan_final_kernel() {
    __shared__ int sh[256];
    int i = blockIdx.x * 256 + threadIdx.x;
    int v = (i < N_NODES) ? g_cnt_dst[i] : 0;
    sh[threadIdx.x] = v;
    __syncthreads();
    for (int s = 1; s < 256; s <<= 1) {
        int t = (threadIdx.x >= s) ? sh[threadIdx.x - s] : 0;
        __syncthreads();
        sh[threadIdx.x] += t;
        __syncthreads();
    }
    if (i < N_NODES) g_rowptr[i] = g_partial[blockIdx.x] + sh[threadIdx.x] - v;
}

__global__ void fill_kernel(const int* __restrict__ ei) {
    int i = blockIdx.x * blockDim.x + threadIdx.x;
    if (i < N_EDGES) {
        int s = ei[i], d = ei[N_EDGES + i];
        int pos = g_rowptr[d] + atomicAdd(&g_cursor[d], 1);
        float w = g_dinv[s] * g_dinv[d];
        g_csr[pos] = make_int2(s, __float_as_int(w));
    }
}

// ---------------- W1 -> fp16 transposed scratch ----------------
__global__ void w1cvt_kernel(const float* __restrict__ W1) {
    int idx = blockIdx.x * 256 + threadIdx.x;
    if (idx < 256 * 512) {
        int n = idx >> 9, k = idx & 511;
        float v = (k < C_IN) ? W1[(size_t)k * HIDDEN + n] : 0.f;
        g_w1h[idx] = __float2half_rn(v);
    }
}

// ---------------- ldmatrix helper ----------------
__device__ __forceinline__ void ldsm_x4(unsigned int& r0, unsigned int& r1,
                                        unsigned int& r2, unsigned int& r3,
                                        unsigned int addr) {
    asm volatile("ldmatrix.sync.aligned.m8n8.x4.shared.b16 {%0,%1,%2,%3}, [%4];"
                 : "=r"(r0), "=r"(r1), "=r"(r2), "=r"(r3) : "r"(addr));
}

// ---------------- FUSED GEMM1+GEMM2 (fp16 mma, BM=128, 512 thr, BK=64, 3-stage) ----------------
#define A16_ST 72
#define A16_BYTES (128 * A16_ST * 2)    /* 18432 */
#define B16_BYTES (256 * A16_ST * 2)    /* 36864 */
#define STAGE_BYTES (A16_BYTES + B16_BYTES)  /* 55296 */
#define SH_ST 264
#define GEMM_SMEM (3 * STAGE_BYTES)     /* 165888; phase2 needs 101376 */
#define G_THREADS 512

__global__ void __launch_bounds__(G_THREADS) gemm12_tc_kernel(
    const float* __restrict__ A, const float* __restrict__ bias,
    const float* __restrict__ W2, const float* __restrict__ b2, const float* __restrict__ temp) {
    extern __shared__ float smem[];
    __half* smh = (__half*)smem;

    const int tid = threadIdx.x;
    const int m0 = blockIdx.x * 128;
    const int wid = tid >> 5, lane = tid & 31;
    const int warp_m = wid >> 2, warp_n = wid & 3;
    const int r = lane >> 2, c = lane & 3;

    const int aRowIn = lane & 15;
    const int aKoff  = (lane >> 4) * 8;
    const int bQuad  = lane >> 3;
    const int bRowIn = lane & 7;
    const int bNloc  = ((bQuad >> 1) * 8) + bRowIn;
    const int bKoff  = (bQuad & 1) * 8;

    float acc[2][8][4];
#pragma unroll
    for (int mt = 0; mt < 2; mt++)
#pragma unroll
        for (int nt = 0; nt < 8; nt++)
#pragma unroll
            for (int i = 0; i < 4; i++) acc[mt][nt][i] = 0.0f;

    float4 astg[4];

    auto bufA16 = [&](int t) { return smh + (t % 3) * (STAGE_BYTES / 2); };
    auto bufB16 = [&](int t) { return smh + (t % 3) * (STAGE_BYTES / 2) + A16_BYTES / 2; };

    auto ldgA = [&](int t) {
        int k0 = t * 64;
#pragma unroll
        for (int j = 0; j < 4; j++) {
            int idx = tid + j * G_THREADS;
            int row = idx >> 4, kv = (idx & 15) * 4;
            int gm = m0 + row, gk = k0 + kv;
            if (gm < N_NODES && gk < C_IN) {
                astg[j] = *(const float4*)(A + (size_t)gm * C_IN + gk);
            } else {
                astg[j] = make_float4(0.f, 0.f, 0.f, 0.f);
            }
        }
    };
    auto stsA = [&](int t) {
        __half* dstb = bufA16(t);
#pragma unroll
        for (int j = 0; j < 4; j++) {
            int idx = tid + j * G_THREADS;
            int row = idx >> 4, kv = (idx & 15) * 4;
            half2 h0 = __floats2half2_rn(astg[j].x, astg[j].y);
            half2 h1 = __floats2half2_rn(astg[j].z, astg[j].w);
            uint2 p;
            p.x = *reinterpret_cast<unsigned int*>(&h0);
            p.y = *reinterpret_cast<unsigned int*>(&h1);
            *(uint2*)(dstb + row * A16_ST + kv) = p;
        }
    };
    auto cpB = [&](int t) {
        __half* dstb = bufB16(t);
        int k0 = t * 64;
#pragma unroll
        for (int j = 0; j < 4; j++) {
            int idx = tid + j * G_THREADS;
            int n = idx >> 3, part = idx & 7;
            const __half* src = g_w1h + (size_t)n * 512 + k0 + part * 8;
            unsigned int dst = (unsigned int)__cvta_generic_to_shared(dstb + n * A16_ST + part * 8);
            asm volatile("cp.async.cg.shared.global [%0], [%1], 16, 16;"
                         :: "r"(dst), "l"(src));
        }
        asm volatile("cp.async.commit_group;");
    };

    const int NT = 8;

    // prologue: stages 0,1 committed; A for stage 2 staged in regs
    ldgA(0); stsA(0); cpB(0);
    ldgA(1); stsA(1); cpB(1);
    ldgA(2);

    for (int t = 0; t < NT; t++) {
        if (t + 1 < NT) { asm volatile("cp.async.wait_group 1;"); }
        else            { asm volatile("cp.async.wait_group 0;"); }
        __syncthreads();

        const __half* sA = bufA16(t);
        const __half* sB = bufB16(t);

        unsigned int aB[2], bB[4];
#pragma unroll
        for (int mt = 0; mt < 2; mt++)
            aB[mt] = (unsigned int)__cvta_generic_to_shared(
                sA + (warp_m * 32 + mt * 16 + aRowIn) * A16_ST + aKoff);
#pragma unroll
        for (int p = 0; p < 4; p++)
            bB[p] = (unsigned int)__cvta_generic_to_shared(
                sB + (warp_n * 64 + p * 16 + bNloc) * A16_ST + bKoff);

#pragma unroll
        for (int ks = 0; ks < 4; ks++) {
            const int off = ks * 32;
            unsigned int af[2][4], bf[8][2];
#pragma unroll
            for (int mt = 0; mt < 2; mt++)
                ldsm_x4(af[mt][0], af[mt][1], af[mt][2], af[mt][3], aB[mt] + off);
#pragma unroll
            for (int p = 0; p < 4; p++)
                ldsm_x4(bf[2 * p][0], bf[2 * p][1], bf[2 * p + 1][0], bf[2 * p + 1][1],
                        bB[p] + off);
#pragma unroll
            for (int mt = 0; mt < 2; mt++)
#pragma unroll
                for (int nt = 0; nt < 8; nt++) {
                    asm volatile(
                        "mma.sync.aligned.m16n8k16.row.col.f32.f16.f16.f32 "
                        "{%0,%1,%2,%3}, {%4,%5,%6,%7}, {%8,%9}, {%0,%1,%2,%3};\n"
                        : "+f"(acc[mt][nt][0]), "+f"(acc[mt][nt][1]),
                          "+f"(acc[mt][nt][2]), "+f"(acc[mt][nt][3])
                        : "r"(af[mt][0]), "r"(af[mt][1]), "r"(af[mt][2]), "r"(af[mt][3]),
                          "r"(bf[nt][0]), "r"(bf[nt][1]));
                }
        }

        // refill stage t+2 (safe: buffer (t+2)%3 was last read in compute(t-1),
        // retired by the sync above); stage A regs for t+3
        if (t + 2 < NT) {
            stsA(t + 2);
            cpB(t + 2);
            if (t + 3 < NT) ldgA(t + 3);
        }
    }
    __syncthreads();

    // ---- stage h tile [128][SH_ST] + W2^T [64][SH_ST] into smem ----
    __half* sH   = smh;
    __half* sW2t = smh + 128 * SH_ST;

#pragma unroll
    for (int mt = 0; mt < 2; mt++) {
#pragma unroll
        for (int nt = 0; nt < 8; nt++) {
            int col = warp_n * 64 + nt * 8 + c * 2;
            float2 bv = *(const float2*)(bias + col);
            int row0 = warp_m * 32 + mt * 16 + r;
            float v0 = fmaxf(acc[mt][nt][0] + bv.x, 0.f);
            float v1 = fmaxf(acc[mt][nt][1] + bv.y, 0.f);
            *(half2*)(sH + row0 * SH_ST + col) = __floats2half2_rn(v0, v1);
            float v2 = fmaxf(acc[mt][nt][2] + bv.x, 0.f);
            float v3 = fmaxf(acc[mt][nt][3] + bv.y, 0.f);
            *(half2*)(sH + (row0 + 8) * SH_ST + col) = __floats2half2_rn(v2, v3);
        }
    }
    for (int idx = tid; idx < 64 * 256; idx += G_THREADS) {
        int n = idx >> 8, k = idx & 255;
        float v = (n < C_OUT) ? __ldg(W2 + (size_t)k * C_OUT + n) : 0.f;
        sW2t[n * SH_ST + k] = __float2half_rn(v);
    }
    __syncthreads();

    // ---- second GEMM ----
    float acc2[2][2][4];
#pragma unroll
    for (int mt = 0; mt < 2; mt++)
#pragma unroll
        for (int nt = 0; nt < 2; nt++)
#pragma unroll
            for (int i = 0; i < 4; i++) acc2[mt][nt][i] = 0.0f;

    unsigned int aB2[2], bB2;
#pragma unroll
    for (int mt = 0; mt < 2; mt++)
        aB2[mt] = (unsigned int)__cvta_generic_to_shared(
            sH + (warp_m * 32 + mt * 16 + aRowIn) * SH_ST + aKoff);
    bB2 = (unsigned int)__cvta_generic_to_shared(
        sW2t + (warp_n * 16 + bNloc) * SH_ST + bKoff);

#pragma unroll
    for (int ks = 0; ks < 16; ks++) {
        const int off = ks * 32;
        unsigned int a[2][4], b[2][2];
#pragma unroll
        for (int mt = 0; mt < 2; mt++)
            ldsm_x4(a[mt][0], a[mt][1], a[mt][2], a[mt][3], aB2[mt] + off);
        ldsm_x4(b[0][0], b[0][1], b[1][0], b[1][1], bB2 + off);
#pragma unroll
        for (int mt = 0; mt < 2; mt++)
#pragma unroll
            for (int nt = 0; nt < 2; nt++) {
                asm volatile(
                    "mma.sync.aligned.m16n8k16.row.col.f32.f16.f16.f32 "
                    "{%0,%1,%2,%3}, {%4,%5,%6,%7}, {%8,%9}, {%0,%1,%2,%3};\n"
                    : "+f"(acc2[mt][nt][0]), "+f"(acc2[mt][nt][1]),
                      "+f"(acc2[mt][nt][2]), "+f"(acc2[mt][nt][3])
                    : "r"(a[mt][0]), "r"(a[mt][1]), "r"(a[mt][2]), "r"(a[mt][3]),
                      "r"(b[nt][0]), "r"(b[nt][1]));
            }
    }

    // ---- epilogue2 ----
    float t0 = __ldg(temp);
#pragma unroll
    for (int mt = 0; mt < 2; mt++) {
#pragma unroll
        for (int nt = 0; nt < 2; nt++) {
            int col = warp_n * 16 + nt * 8 + c * 2;
#pragma unroll
            for (int hh = 0; hh < 2; hh++) {
                int gm = m0 + warp_m * 32 + mt * 16 + hh * 8 + r;
                if (gm >= N_NODES) continue;
                __half* arow = g_bufA + (size_t)gm * C_PAD;
                if (col < C_OUT) {
                    float v0 = acc2[mt][nt][hh * 2 + 0] + __ldg(b2 + col);
                    float v1 = acc2[mt][nt][hh * 2 + 1] + __ldg(b2 + col + 1);
                    *(half2*)(arow + col) = __floats2half2_rn(v0, v1);
                    float* hrow = g_hidden + (size_t)gm * C_OUT + col;
                    hrow[0] = t0 * v0;
                    hrow[1] = t0 * v1;
                } else {
                    *(half2*)(arow + col) = __floats2half2_rn(0.f, 0.f);
                }
            }
        }
    }
}

// ---------------- pull hop 1 (R10 form): bufB[d] = sum w * bufA[src] ----------------
__global__ void __launch_bounds__(256) pull1_kernel() {
    int node = (blockIdx.x * blockDim.x + threadIdx.x) >> 5;
    int lane = threadIdx.x & 31;
    if (node >= N_NODES) return;
    int beg = g_rowptr[node], end = g_rowptr[node + 1];
    float a0 = 0.f, a1 = 0.f;
    int e = beg;
    for (; e + 3 < end; e += 4) {
        int2 e0 = g_csr[e], e1 = g_csr[e + 1], e2 = g_csr[e + 2], e3 = g_csr[e + 3];
        half2 h0 = *(const half2*)(g_bufA + (size_t)e0.x * C_PAD + lane * 2);
        half2 h1 = *(const half2*)(g_bufA + (size_t)e1.x * C_PAD + lane * 2);
        half2 h2 = *(const half2*)(g_bufA + (size_t)e2.x * C_PAD + lane * 2);
        half2 h3 = *(const half2*)(g_bufA + (size_t)e3.x * C_PAD + lane * 2);
        float2 f0 = __half22float2(h0), f1 = __half22float2(h1);
        float2 f2 = __half22float2(h2), f3 = __half22float2(h3);
        float w0 = __int_as_float(e0.y), w1 = __int_as_float(e1.y);
        float w2 = __int_as_float(e2.y), w3 = __int_as_float(e3.y);
        a0 += w0 * f0.x + w1 * f1.x + w2 * f2.x + w3 * f3.x;
        a1 += w0 * f0.y + w1 * f1.y + w2 * f2.y + w3 * f3.y;
    }
    for (; e < end; e++) {
        int2 ed = g_csr[e];
        half2 hv = *(const half2*)(g_bufA + (size_t)ed.x * C_PAD + lane * 2);
        float2 fv = __half22float2(hv);
        float w = __int_as_float(ed.y);
        a0 += w * fv.x;
        a1 += w * fv.y;
    }
    *(half2*)(g_bufB + (size_t)node * C_PAD + lane * 2) = __floats2half2_rn(a0, a1);
}

// ---------------- pull hop 2 + axpy (R10 form, non-final hops) ----------------
__global__ void __launch_bounds__(256) pull2_kernel(const float* __restrict__ temp, int kidx) {
    int node = (blockIdx.x * blockDim.x + threadIdx.x) >> 5;
    int lane = threadIdx.x & 31;
    if (node >= N_NODES) return;
    float t = temp[kidx];
    int beg = g_rowptr[node], end = g_rowptr[node + 1];
    float a0 = 0.f, a1 = 0.f;
    int e = beg;
    for (; e + 3 < end; e += 4) {
        int2 e0 = g_csr[e], e1 = g_csr[e + 1], e2 = g_csr[e + 2], e3 = g_csr[e + 3];
        half2 h0 = *(const half2*)(g_bufB + (size_t)e0.x * C_PAD + lane * 2);
        half2 h1 = *(const half2*)(g_bufB + (size_t)e1.x * C_PAD + lane * 2);
        half2 h2 = *(const half2*)(g_bufB + (size_t)e2.x * C_PAD + lane * 2);
        half2 h3 = *(const half2*)(g_bufB + (size_t)e3.x * C_PAD + lane * 2);
        float2 f0 = __half22float2(h0), f1 = __half22float2(h1);
        float2 f2 = __half22float2(h2), f3 = __half22float2(h3);
        float w0 = __int_as_float(e0.y), w1 = __int_as_float(e1.y);
        float w2 = __int_as_float(e2.y), w3 = __int_as_float(e3.y);
        a0 += w0 * f0.x + w1 * f1.x + w2 * f2.x + w3 * f3.x;
        a1 += w0 * f0.y + w1 * f1.y + w2 * f2.y + w3 * f3.y;
    }
    for (; e < end; e++) {
        int2 ed = g_csr[e];
        half2 hv = *(const half2*)(g_bufB + (size_t)ed.x * C_PAD + lane * 2);
        float2 fv = __half22float2(hv);
        float w = __int_as_float(ed.y);
        a0 += w * fv.x;
        a1 += w * fv.y;
    }
    *(half2*)(g_bufA + (size_t)node * C_PAD + lane * 2) = __floats2half2_rn(a0, a1);
    if (lane < C_OUT / 2) {
        float* hrow = g_hidden + (size_t)node * C_OUT + lane * 2;
        hrow[0] += t * a0;
        hrow[1] += t * a1;
    }
}

// ---------------- final pull2 + axpy + log_softmax + counter-reset for next replay ----------------
__global__ void __launch_bounds__(256) pull2_final_kernel(
    const float* __restrict__ temp, float* __restrict__ out) {
    int gtid = blockIdx.x * blockDim.x + threadIdx.x;
    // zero the counters consumed at the START of the next replay (no reader of
    // these arrays remains in this launch)
    if (gtid < N_NODES) { g_cnt_src[gtid] = 0; g_cnt_dst[gtid] = 0; g_cursor[gtid] = 0; }

    int node = gtid >> 5;
    int lane = threadIdx.x & 31;
    if (node >= N_NODES) return;
    float t = temp[K_HALF];
    int beg = g_rowptr[node], end = g_rowptr[node + 1];
    float a0 = 0.f, a1 = 0.f;
    int e = beg;
    for (; e + 3 < end; e += 4) {
        int2 e0 = g_csr[e], e1 = g_csr[e + 1], e2 = g_csr[e + 2], e3 = g_csr[e + 3];
        half2 h0 = *(const half2*)(g_bufB + (size_t)e0.x * C_PAD + lane * 2);
        half2 h1 = *(const half2*)(g_bufB + (size_t)e1.x * C_PAD + lane * 2);
        half2 h2 = *(const half2*)(g_bufB + (size_t)e2.x * C_PAD + lane * 2);
        half2 h3 = *(const half2*)(g_bufB + (size_t)e3.x * C_PAD + lane * 2);
        float2 f0 = __half22float2(h0), f1 = __half22float2(h1);
        float2 f2 = __half22float2(h2), f3 = __half22float2(h3);
        float w0 = __int_as_float(e0.y), w1 = __int_as_float(e1.y);
        float w2 = __int_as_float(e2.y), w3 = __int_as_float(e3.y);
        a0 += w0 * f0.x + w1 * f1.x + w2 * f2.x + w3 * f3.x;
        a1 += w0 * f0.y + w1 * f1.y + w2 * f2.y + w3 * f3.y;
    }
    for (; e < end; e++) {
        int2 ed = g_csr[e];
        half2 hv = *(const half2*)(g_bufB + (size_t)ed.x * C_PAD + lane * 2);
        float2 fv = __half22float2(hv);
        float w = __int_as_float(ed.y);
        a0 += w * fv.x;
        a1 += w * fv.y;
    }
    float v0 = 0.f, v1 = 0.f;
    if (lane < C_OUT / 2) {
        float2 hp = *(const float2*)(g_hidden + (size_t)node * C_OUT + lane * 2);
        v0 = hp.x + t * a0;
        v1 = hp.y + t * a1;
    }
    float m = (lane < C_OUT / 2) ? fmaxf(v0, v1) : -INFINITY;
#pragma unroll
    for (int o = 16; o > 0; o >>= 1) m = fmaxf(m, __shfl_xor_sync(0xffffffffu, m, o));
    float s = (lane < C_OUT / 2) ? (expf(v0 - m) + expf(v1 - m)) : 0.f;
#pragma unroll
    for (int o = 16; o > 0; o >>= 1) s += __shfl_xor_sync(0xffffffffu, s, o);
    float l = m + logf(s);
    if (lane < C_OUT / 2) {
        float2 o2;
        o2.x = v0 - l;
        o2.y = v1 - l;
        *(float2*)(out + (size_t)node * C_OUT + lane * 2) = o2;
    }
}

// ---------------- launch ----------------
extern "C" void kernel_launch(void* const* d_in, const int* in_sizes, int n_in,
                              void* d_out, int out_size) {
    const float* x    = (const float*)d_in[0];
    const int*   ei   = (const int*)d_in[1];
    const float* W1   = (const float*)d_in[2];
    const float* b1   = (const float*)d_in[3];
    const float* W2   = (const float*)d_in[4];
    const float* b2   = (const float*)d_in[5];
    const float* temp = (const float*)d_in[6];
    float* out = (float*)d_out;

    int nb_edges = (N_EDGES + 255) / 256;

    static int attr_set = 0;
    if (!attr_set) {
        cudaFuncSetAttribute(gemm12_tc_kernel, cudaFuncAttributeMaxDynamicSharedMemorySize, GEMM_SMEM);
        attr_set = 1;
    }

    w1cvt_kernel<<<512, 256>>>(W1);                                           // 0
    count_kernel<<<nb_edges, 256>>>(ei);                                      // 1
    scan_partial_kernel<<<NB_SCAN, 256>>>();                                  // 2 (incl dinv)
    gemm12_tc_kernel<<<(N_NODES + 127) / 128, G_THREADS, GEMM_SMEM>>>(x, b1, W2, b2, temp);  // 3 <- profiled
    scan_offsets_kernel<<<1, 1>>>();                                          // 4
    scan_final_kernel<<<NB_SCAN, 256>>>();                                    // 5
    fill_kernel<<<nb_edges, 256>>>(ei);                                       // 6

    int pull_grid = (N_NODES * 32 + 255) / 256;
    for (int k = 0; k < K_HALF - 1; k++) {
        pull1_kernel<<<pull_grid, 256>>>();
        pull2_kernel<<<pull_grid, 256>>>(temp, k + 1);
    }
    pull1_kernel<<<pull_grid, 256>>>();
    pull2_final_kernel<<<pull_grid, 256>>>(temp, out);
}